// round 2
// baseline (speedup 1.0000x reference)
#include <cuda_runtime.h>
#include <float.h>

#define BB 2
#define HH 12
#define NN 1600
#define DD 32
#define GG 48
#define KT 96
#define CC 384
#define BHc (BB*HH)          // 24
#define NQ (BHc*NN)          // 38400
#define NROW (BHc*GG)        // 1152

// Scratch (no cudaMalloc allowed)
__device__ float g_qkv[3][BHc*NN*DD];      // [which][b*h][n][d]
__device__ int   g_gidx[NQ];
__device__ float g_qsum[NROW*DD];
__device__ int   g_cnt[NROW];
__device__ int   g_topk[NROW*KT];
__device__ int   g_qlist[NROW*NN];         // query indices per (bh,g)
__device__ float g_att[BB*NN*HH*DD];       // [b][n][h][d]

__global__ void zero_kernel() {
    int i = blockIdx.x*blockDim.x + threadIdx.x;
    if (i < NROW*DD) g_qsum[i] = 0.f;
    if (i < NROW)    g_cnt[i] = 0;
}

// out[m][col] = sum_k A[m][k] * B[col][k]   (NT GEMM, K=384, M=3200)
// MODE 0: A = x, scatter into g_qkv.  MODE 1: A = g_att, write d_out.
template<int MODE>
__global__ void gemm_nt(const float* __restrict__ A, const float* __restrict__ B,
                        float* __restrict__ out) {
    const int K = CC;
    __shared__ float As[16][128];
    __shared__ float Bs[16][128];
    const float* Ap = (MODE == 0) ? A : (const float*)g_att;
    int m0 = blockIdx.y * 128, n0 = blockIdx.x * 128;
    int tid = threadIdx.x;
    int tx = tid & 15, ty = tid >> 4;
    float acc[8][8] = {};
    for (int k0 = 0; k0 < K; k0 += 16) {
        #pragma unroll
        for (int s = 0; s < 2; s++) {
            int slot = tid + s * 256;
            int r = slot >> 2, c4 = (slot & 3) << 2;
            float4 va = *(const float4*)(Ap + (size_t)(m0 + r)*K + k0 + c4);
            As[c4+0][r] = va.x; As[c4+1][r] = va.y; As[c4+2][r] = va.z; As[c4+3][r] = va.w;
            float4 vb = *(const float4*)(B + (size_t)(n0 + r)*K + k0 + c4);
            Bs[c4+0][r] = vb.x; Bs[c4+1][r] = vb.y; Bs[c4+2][r] = vb.z; Bs[c4+3][r] = vb.w;
        }
        __syncthreads();
        #pragma unroll
        for (int kk = 0; kk < 16; kk++) {
            float a[8], b[8];
            *(float4*)&a[0] = *(const float4*)&As[kk][ty*8];
            *(float4*)&a[4] = *(const float4*)&As[kk][ty*8+4];
            *(float4*)&b[0] = *(const float4*)&Bs[kk][tx*8];
            *(float4*)&b[4] = *(const float4*)&Bs[kk][tx*8+4];
            #pragma unroll
            for (int i = 0; i < 8; i++)
                #pragma unroll
                for (int j = 0; j < 8; j++)
                    acc[i][j] += a[i] * b[j];
        }
        __syncthreads();
    }
    #pragma unroll
    for (int i = 0; i < 8; i++) {
        int m = m0 + ty*8 + i;
        int bi = m / NN, n = m % NN;
        #pragma unroll
        for (int j = 0; j < 8; j++) {
            int col = n0 + tx*8 + j;
            if (MODE == 0) {
                int which = col / (HH*DD);
                int r2 = col % (HH*DD);
                int head = r2 / DD, dd = r2 % DD;
                g_qkv[which][(((size_t)bi*HH + head)*NN + n)*DD + dd] = acc[i][j];
            } else {
                out[(size_t)m*(HH*DD) + col] = acc[i][j];
            }
        }
    }
}

// One warp per query. Lane-per-group argmax (first-max tie-break = jnp.argmax),
// accumulate group sums/counts, append query to its group's list.
__global__ void route_kernel(const float* __restrict__ w_gp) {
    __shared__ float sgp[GG][33];
    int tid = threadIdx.x;
    int qid = blockIdx.x * 8 + (tid >> 5);
    int lane = tid & 31;
    int bh = qid / NN, n = qid % NN;
    int h = bh % HH;
    // whole block is same h (200 blocks per bh)
    for (int i = tid; i < GG*DD; i += 256)
        sgp[i >> 5][i & 31] = w_gp[h*GG*DD + i];
    __syncthreads();
    float qv = g_qkv[0][((size_t)bh*NN + n)*DD + lane];
    float s0 = 0.f, s1 = 0.f;
    #pragma unroll
    for (int d = 0; d < DD; d++) {
        float qd = __shfl_sync(0xffffffffu, qv, d);
        s0 += qd * sgp[lane][d];
        if (lane < 16) s1 += qd * sgp[lane + 32][d];
    }
    // best (val, group) with lowest-group tie-break
    float bv = s0; int bg = lane;
    if (lane < 16 && (s1 > bv)) { bv = s1; bg = lane + 32; }
    #pragma unroll
    for (int o = 16; o; o >>= 1) {
        float ov = __shfl_xor_sync(0xffffffffu, bv, o);
        int   og = __shfl_xor_sync(0xffffffffu, bg, o);
        if (ov > bv || (ov == bv && og < bg)) { bv = ov; bg = og; }
    }
    bg = __shfl_sync(0xffffffffu, bg, 0);
    int row = bh*GG + bg;
    if (lane == 0) {
        g_gidx[qid] = bg;
        int p = atomicAdd(&g_cnt[row], 1);
        g_qlist[row*NN + p] = n;
    }
    atomicAdd(&g_qsum[row*DD + lane], qv);
}

__device__ __forceinline__ unsigned f2u_mono(float f) {
    unsigned u = __float_as_uint(f);
    return u ^ (((int)u >> 31) | 0x80000000u);
}

// One block per (bh, 4 groups): fold qmean, compute qmw scores, radix-select top-96.
#define GPB 4
__global__ void qmw_topk_kernel() {
    int blk = blockIdx.x;                 // [0, BHc * GG/GPB) = 288
    int bh = blk / (GG/GPB);
    int g0 = (blk % (GG/GPB)) * GPB;
    __shared__ float qm[GPB][DD];
    __shared__ unsigned uv[GPB][NN];
    __shared__ unsigned hist[256];
    __shared__ int s_selb, s_k, s_nout, s_neq;
    __shared__ int eqlist[NN];
    int tid = threadIdx.x, lane = tid & 31;

    if (tid < GPB*DD) {
        int row = bh*GG + g0 + tid/DD;
        float c = (float)g_cnt[row];
        qm[tid/DD][tid & 31] = g_qsum[row*DD + (tid & 31)] / fmaxf(c, 1e-8f);
    }
    __syncthreads();

    const float* kb = &g_qkv[1][(size_t)bh*NN*DD];
    for (int m = tid; m < NN; m += 256) {
        float kr[DD];
        #pragma unroll
        for (int t = 0; t < 8; t++) {
            float4 v = *(const float4*)(kb + (size_t)m*DD + 4*t);
            kr[4*t] = v.x; kr[4*t+1] = v.y; kr[4*t+2] = v.z; kr[4*t+3] = v.w;
        }
        #pragma unroll
        for (int g = 0; g < GPB; g++) {
            float s = 0.f;
            #pragma unroll
            for (int d = 0; d < DD; d++) s += qm[g][d] * kr[d];
            uv[g][m] = f2u_mono(s);
        }
    }
    __syncthreads();

    for (int g = 0; g < GPB; g++) {
        int row = bh*GG + g0 + g;
        unsigned prefix = 0;
        int k = KT;
        #pragma unroll
        for (int pass = 0; pass < 4; pass++) {
            int shift = 24 - 8*pass;
            hist[tid] = 0;
            __syncthreads();
            for (int m = tid; m < NN; m += 256) {
                unsigned u = uv[g][m];
                bool cand = (pass == 0) || ((u >> (shift+8)) == (prefix >> (shift+8)));
                if (cand) atomicAdd(&hist[(u >> shift) & 255], 1u);
            }
            __syncthreads();
            if (tid < 32) {
                // lane owns bins [lane*8, lane*8+8): within-lane suffix sums
                unsigned hv[8], loc[8];
                unsigned s = 0;
                #pragma unroll
                for (int i = 7; i >= 0; i--) {
                    hv[i] = hist[lane*8 + i];
                    s += hv[i];
                    loc[i] = s;
                }
                // inclusive suffix scan across lanes
                unsigned run = s;
                #pragma unroll
                for (int o = 1; o < 32; o <<= 1) {
                    unsigned t = __shfl_down_sync(0xffffffffu, run, o);
                    if (lane + o < 32) run += t;
                }
                unsigned above = run - s;  // count in lanes > me
                #pragma unroll
                for (int i = 0; i < 8; i++) {
                    unsigned S  = above + loc[i];           // count >= bin
                    unsigned gt = S - hv[i];                // count > bin
                    if ((unsigned)k <= S && (unsigned)k > gt) {
                        s_selb = lane*8 + i;
                        s_k    = k - (int)gt;
                    }
                }
            }
            __syncthreads();
            prefix |= (unsigned)s_selb << shift;
            k = s_k;
            __syncthreads();
        }
        unsigned uT = prefix;
        int k_rem = k;
        if (tid == 0) { s_nout = 0; s_neq = 0; }
        __syncthreads();
        for (int m = tid; m < NN; m += 256) {
            unsigned u = uv[g][m];
            if (u > uT) {
                int p = atomicAdd(&s_nout, 1);
                g_topk[row*KT + p] = m;
            } else if (u == uT) {
                int p = atomicAdd(&s_neq, 1);
                eqlist[p] = m;
            }
        }
        __syncthreads();
        if (tid == 0) {
            int base = s_nout, ne = s_neq;
            for (int t = 0; t < k_rem; t++) {
                int mi = 1 << 30, mp = 0;
                for (int e = 0; e < ne; e++)
                    if (eqlist[e] < mi) { mi = eqlist[e]; mp = e; }
                eqlist[mp] = 1 << 30;
                g_topk[row*KT + base + t] = mi;
            }
        }
        __syncthreads();
    }
}

// One block per (bh,g): stage the group's 96 K/V rows in smem, then each warp
// processes queries of the group: scores + softmax + weighted V sum.
__global__ void attn_kernel() {
    int row = blockIdx.x;              // [0, NROW)
    int bh = row / GG;
    int bi = bh / HH, h = bh % HH;
    __shared__ float Kt[DD][97];       // [d][key]
    __shared__ float Vs[KT][33];       // [key][d]
    int tid = threadIdx.x, w = tid >> 5, lane = tid & 31;
    const int* tk = &g_topk[row*KT];
    const float* kb = &g_qkv[1][(size_t)bh*NN*DD];
    const float* vb = &g_qkv[2][(size_t)bh*NN*DD];
    for (int j = w; j < KT; j += 8) {
        int idx = tk[j];
        Kt[lane][j] = kb[(size_t)idx*DD + lane];
        Vs[j][lane] = vb[(size_t)idx*DD + lane];
    }
    int cnt = g_cnt[row];
    __syncthreads();
    const int* ql = &g_qlist[row*NN];
    const float* qb = &g_qkv[0][(size_t)bh*NN*DD];
    const float scale = 0.17677669529663687f;  // 32^-0.5
    for (int i = w; i < cnt; i += 8) {
        int n = ql[i];
        float qv = qb[(size_t)n*DD + lane];
        float s0 = 0.f, s1 = 0.f, s2 = 0.f;
        #pragma unroll
        for (int d = 0; d < DD; d++) {
            float qd = __shfl_sync(0xffffffffu, qv, d);
            s0 += qd * Kt[d][lane];
            s1 += qd * Kt[d][lane + 32];
            s2 += qd * Kt[d][lane + 64];
        }
        s0 *= scale; s1 *= scale; s2 *= scale;
        float mx = fmaxf(s0, fmaxf(s1, s2));
        #pragma unroll
        for (int o = 16; o; o >>= 1) mx = fmaxf(mx, __shfl_xor_sync(0xffffffffu, mx, o));
        float e0 = __expf(s0 - mx), e1 = __expf(s1 - mx), e2 = __expf(s2 - mx);
        float ps = e0 + e1 + e2;
        #pragma unroll
        for (int o = 16; o; o >>= 1) ps += __shfl_xor_sync(0xffffffffu, ps, o);
        float inv = 1.f / ps;
        float acc = 0.f;
        #pragma unroll
        for (int j = 0; j < KT; j++) {
            float pj = __shfl_sync(0xffffffffu, (j < 32) ? e0 : ((j < 64) ? e1 : e2), j & 31);
            acc += pj * Vs[j][lane];
        }
        acc *= inv;
        g_att[(((size_t)bi*NN + n)*HH + h)*DD + lane] = acc;
    }
}

extern "C" void kernel_launch(void* const* d_in, const int* in_sizes, int n_in,
                              void* d_out, int out_size) {
    const float* x      = (const float*)d_in[0];
    const float* w_qkv  = (const float*)d_in[1];
    const float* w_gp   = (const float*)d_in[2];
    const float* w_proj = (const float*)d_in[3];
    float* out = (float*)d_out;

    zero_kernel<<<144, 256>>>();
    gemm_nt<0><<<dim3(9, 25), 256>>>(x, w_qkv, nullptr);       // QKV: 3200x1152x384
    route_kernel<<<NQ/8, 256>>>(w_gp);
    qmw_topk_kernel<<<BHc*(GG/GPB), 256>>>();
    attn_kernel<<<NROW, 256>>>();
    gemm_nt<1><<<dim3(3, 25), 256>>>(nullptr, w_proj, out);    // proj: 3200x384x384
}

// round 3
// speedup vs baseline: 3.0494x; 3.0494x over previous
#include <cuda_runtime.h>
#include <float.h>

#define BB 2
#define HH 12
#define NN 1600
#define DD 32
#define GG 48
#define KT 96
#define CC 384
#define BHc (BB*HH)          // 24
#define NQ (BHc*NN)          // 38400
#define NROW (BHc*GG)        // 1152

// Scratch (no cudaMalloc allowed)
__device__ float g_qkv[3][BHc*NN*DD];      // [which][b*h][n][d]
__device__ int   g_gidx[NQ];
__device__ float g_qsum[NROW*DD];
__device__ int   g_cnt[NROW];
__device__ int   g_topk[NROW*KT];
__device__ int   g_qlist[NROW*NN];         // query indices per (bh,g)
__device__ float g_att[BB*NN*HH*DD];       // [b][n][h][d]

__global__ void zero_kernel() {
    int i = blockIdx.x*blockDim.x + threadIdx.x;
    if (i < NROW*DD) g_qsum[i] = 0.f;
    if (i < NROW)    g_cnt[i] = 0;
}

// out[m][col] = sum_k A[m][k] * B[col][k]   (NT GEMM, K=384, M=3200)
// MODE 0: A = x, scatter into g_qkv.  MODE 1: A = g_att, write d_out.
template<int MODE>
__global__ void gemm_nt(const float* __restrict__ A, const float* __restrict__ B,
                        float* __restrict__ out) {
    const int K = CC;
    __shared__ float As[16][128];
    __shared__ float Bs[16][128];
    const float* Ap = (MODE == 0) ? A : (const float*)g_att;
    int m0 = blockIdx.y * 128, n0 = blockIdx.x * 128;
    int tid = threadIdx.x;
    int tx = tid & 15, ty = tid >> 4;
    float acc[8][8] = {};
    for (int k0 = 0; k0 < K; k0 += 16) {
        #pragma unroll
        for (int s = 0; s < 2; s++) {
            int slot = tid + s * 256;
            int r = slot >> 2, c4 = (slot & 3) << 2;
            float4 va = *(const float4*)(Ap + (size_t)(m0 + r)*K + k0 + c4);
            As[c4+0][r] = va.x; As[c4+1][r] = va.y; As[c4+2][r] = va.z; As[c4+3][r] = va.w;
            float4 vb = *(const float4*)(B + (size_t)(n0 + r)*K + k0 + c4);
            Bs[c4+0][r] = vb.x; Bs[c4+1][r] = vb.y; Bs[c4+2][r] = vb.z; Bs[c4+3][r] = vb.w;
        }
        __syncthreads();
        #pragma unroll
        for (int kk = 0; kk < 16; kk++) {
            float a[8], b[8];
            *(float4*)&a[0] = *(const float4*)&As[kk][ty*8];
            *(float4*)&a[4] = *(const float4*)&As[kk][ty*8+4];
            *(float4*)&b[0] = *(const float4*)&Bs[kk][tx*8];
            *(float4*)&b[4] = *(const float4*)&Bs[kk][tx*8+4];
            #pragma unroll
            for (int i = 0; i < 8; i++)
                #pragma unroll
                for (int j = 0; j < 8; j++)
                    acc[i][j] += a[i] * b[j];
        }
        __syncthreads();
    }
    #pragma unroll
    for (int i = 0; i < 8; i++) {
        int m = m0 + ty*8 + i;
        int bi = m / NN, n = m % NN;
        #pragma unroll
        for (int j = 0; j < 8; j++) {
            int col = n0 + tx*8 + j;
            if (MODE == 0) {
                int which = col / (HH*DD);
                int r2 = col % (HH*DD);
                int head = r2 / DD, dd = r2 % DD;
                g_qkv[which][(((size_t)bi*HH + head)*NN + n)*DD + dd] = acc[i][j];
            } else {
                out[(size_t)m*(HH*DD) + col] = acc[i][j];
            }
        }
    }
}

// One warp per query. Lane-per-group argmax (first-max tie-break = jnp.argmax),
// accumulate group sums/counts, append query to its group's list.
__global__ void route_kernel(const float* __restrict__ w_gp) {
    __shared__ float sgp[GG][33];
    int tid = threadIdx.x;
    int qid = blockIdx.x * 8 + (tid >> 5);
    int lane = tid & 31;
    int bh = qid / NN, n = qid % NN;
    int h = bh % HH;
    // whole block is same h (200 blocks per bh)
    for (int i = tid; i < GG*DD; i += 256)
        sgp[i >> 5][i & 31] = w_gp[h*GG*DD + i];
    __syncthreads();
    float qv = g_qkv[0][((size_t)bh*NN + n)*DD + lane];
    float s0 = 0.f, s1 = 0.f;
    #pragma unroll
    for (int d = 0; d < DD; d++) {
        float qd = __shfl_sync(0xffffffffu, qv, d);
        s0 += qd * sgp[lane][d];
        if (lane < 16) s1 += qd * sgp[lane + 32][d];
    }
    // best (val, group) with lowest-group tie-break
    float bv = s0; int bg = lane;
    if (lane < 16 && (s1 > bv)) { bv = s1; bg = lane + 32; }
    #pragma unroll
    for (int o = 16; o; o >>= 1) {
        float ov = __shfl_xor_sync(0xffffffffu, bv, o);
        int   og = __shfl_xor_sync(0xffffffffu, bg, o);
        if (ov > bv || (ov == bv && og < bg)) { bv = ov; bg = og; }
    }
    bg = __shfl_sync(0xffffffffu, bg, 0);
    int row = bh*GG + bg;
    if (lane == 0) {
        g_gidx[qid] = bg;
        int p = atomicAdd(&g_cnt[row], 1);
        g_qlist[row*NN + p] = n;
    }
    atomicAdd(&g_qsum[row*DD + lane], qv);
}

__device__ __forceinline__ unsigned f2u_mono(float f) {
    unsigned u = __float_as_uint(f);
    return u ^ (((int)u >> 31) | 0x80000000u);
}

// One block per (bh, 4 groups): fold qmean, compute qmw scores, radix-select top-96.
// Empty groups are skipped entirely (their topk list is never consumed).
#define GPB 4
__global__ void qmw_topk_kernel() {
    int blk = blockIdx.x;                 // [0, BHc * GG/GPB) = 288
    int bh = blk / (GG/GPB);
    int g0 = (blk % (GG/GPB)) * GPB;
    __shared__ float qm[GPB][DD];
    __shared__ unsigned uv[GPB][NN];
    __shared__ unsigned hist[256];
    __shared__ int s_selb, s_k, s_nout;
    __shared__ int warp_sums[8];
    __shared__ int s_cnt[GPB];
    int tid = threadIdx.x, lane = tid & 31, w = tid >> 5;

    if (tid < GPB) s_cnt[tid] = g_cnt[bh*GG + g0 + tid];
    if (tid < GPB*DD) {
        int row = bh*GG + g0 + tid/DD;
        float c = (float)g_cnt[row];
        qm[tid/DD][tid & 31] = g_qsum[row*DD + (tid & 31)] / fmaxf(c, 1e-8f);
    }
    __syncthreads();

    const float* kb = &g_qkv[1][(size_t)bh*NN*DD];
    for (int m = tid; m < NN; m += 256) {
        float kr[DD];
        #pragma unroll
        for (int t = 0; t < 8; t++) {
            float4 v = *(const float4*)(kb + (size_t)m*DD + 4*t);
            kr[4*t] = v.x; kr[4*t+1] = v.y; kr[4*t+2] = v.z; kr[4*t+3] = v.w;
        }
        #pragma unroll
        for (int g = 0; g < GPB; g++) {
            float s = 0.f;
            #pragma unroll
            for (int d = 0; d < DD; d++) s += qm[g][d] * kr[d];
            uv[g][m] = f2u_mono(s);
        }
    }
    __syncthreads();

    for (int g = 0; g < GPB; g++) {
        if (s_cnt[g] == 0) continue;      // uniform across block: group unused
        int row = bh*GG + g0 + g;
        unsigned prefix = 0;
        int k = KT;
        #pragma unroll
        for (int pass = 0; pass < 4; pass++) {
            int shift = 24 - 8*pass;
            hist[tid] = 0;
            __syncthreads();
            for (int m = tid; m < NN; m += 256) {
                unsigned u = uv[g][m];
                bool cand = (pass == 0) || ((u >> (shift+8)) == (prefix >> (shift+8)));
                if (cand) atomicAdd(&hist[(u >> shift) & 255], 1u);
            }
            __syncthreads();
            if (tid < 32) {
                // lane owns bins [lane*8, lane*8+8): within-lane suffix sums
                unsigned hv[8], loc[8];
                unsigned s = 0;
                #pragma unroll
                for (int i = 7; i >= 0; i--) {
                    hv[i] = hist[lane*8 + i];
                    s += hv[i];
                    loc[i] = s;
                }
                // inclusive suffix scan across lanes
                unsigned run = s;
                #pragma unroll
                for (int o = 1; o < 32; o <<= 1) {
                    unsigned t = __shfl_down_sync(0xffffffffu, run, o);
                    if (lane + o < 32) run += t;
                }
                unsigned above = run - s;  // count in lanes > me
                #pragma unroll
                for (int i = 0; i < 8; i++) {
                    unsigned S  = above + loc[i];           // count >= bin
                    unsigned gt = S - hv[i];                // count > bin
                    if ((unsigned)k <= S && (unsigned)k > gt) {
                        s_selb = lane*8 + i;
                        s_k    = k - (int)gt;
                    }
                }
            }
            __syncthreads();
            prefix |= (unsigned)s_selb << shift;
            k = s_k;
            __syncthreads();
        }
        unsigned uT = prefix;
        int k_rem = k;                     // how many of the == uT set to keep
        if (tid == 0) s_nout = 0;
        __syncthreads();
        // strictly-greater: order in g_topk is irrelevant (mask semantics)
        for (int m = tid; m < NN; m += 256) {
            if (uv[g][m] > uT) {
                int p = atomicAdd(&s_nout, 1);
                g_topk[row*KT + p] = m;
            }
        }
        __syncthreads();
        int base = s_nout;                 // == KT - k_rem
        // equals: keep the k_rem LOWEST indices (lax.top_k stable tie-break).
        // Parallel ordered compaction over contiguous per-thread chunks.
        const int CH = (NN + 255) / 256;   // 7
        int lo = tid * CH;
        int hi = lo + CH; if (hi > NN) hi = NN; if (lo > NN) lo = NN;
        int c_loc = 0;
        for (int m = lo; m < hi; m++) if (uv[g][m] == uT) c_loc++;
        int v = c_loc;
        #pragma unroll
        for (int o = 1; o < 32; o <<= 1) {
            int t = __shfl_up_sync(0xffffffffu, v, o);
            if (lane >= o) v += t;
        }
        if (lane == 31) warp_sums[w] = v;
        __syncthreads();
        int woff = 0;
        #pragma unroll
        for (int ww = 0; ww < 8; ww++) if (ww < w) woff += warp_sums[ww];
        int rank = woff + v - c_loc;       // exclusive prefix in index order
        for (int m = lo; m < hi; m++) {
            if (uv[g][m] == uT) {
                if (rank < k_rem) g_topk[row*KT + base + rank] = m;
                rank++;
            }
        }
        __syncthreads();
    }
}

// One block per (bh,g): stage the group's 96 K/V rows in smem, then each warp
// processes queries of the group: scores + softmax + weighted V sum.
__global__ void attn_kernel() {
    int row = blockIdx.x;              // [0, NROW)
    int cnt = g_cnt[row];
    if (cnt == 0) return;              // uniform: whole block exits together
    int bh = row / GG;
    int bi = bh / HH, h = bh % HH;
    __shared__ float Kt[DD][97];       // [d][key]
    __shared__ float Vs[KT][33];       // [key][d]
    int tid = threadIdx.x, w = tid >> 5, lane = tid & 31;
    const int* tk = &g_topk[row*KT];
    const float* kb = &g_qkv[1][(size_t)bh*NN*DD];
    const float* vb = &g_qkv[2][(size_t)bh*NN*DD];
    for (int j = w; j < KT; j += 8) {
        int idx = tk[j];
        Kt[lane][j] = kb[(size_t)idx*DD + lane];
        Vs[j][lane] = vb[(size_t)idx*DD + lane];
    }
    __syncthreads();
    const int* ql = &g_qlist[row*NN];
    const float* qb = &g_qkv[0][(size_t)bh*NN*DD];
    const float scale = 0.17677669529663687f;  // 32^-0.5
    for (int i = w; i < cnt; i += 8) {
        int n = ql[i];
        float qv = qb[(size_t)n*DD + lane];
        float s0 = 0.f, s1 = 0.f, s2 = 0.f;
        #pragma unroll
        for (int d = 0; d < DD; d++) {
            float qd = __shfl_sync(0xffffffffu, qv, d);
            s0 += qd * Kt[d][lane];
            s1 += qd * Kt[d][lane + 32];
            s2 += qd * Kt[d][lane + 64];
        }
        s0 *= scale; s1 *= scale; s2 *= scale;
        float mx = fmaxf(s0, fmaxf(s1, s2));
        #pragma unroll
        for (int o = 16; o; o >>= 1) mx = fmaxf(mx, __shfl_xor_sync(0xffffffffu, mx, o));
        float e0 = __expf(s0 - mx), e1 = __expf(s1 - mx), e2 = __expf(s2 - mx);
        float ps = e0 + e1 + e2;
        #pragma unroll
        for (int o = 16; o; o >>= 1) ps += __shfl_xor_sync(0xffffffffu, ps, o);
        float inv = 1.f / ps;
        float acc = 0.f;
        #pragma unroll
        for (int j = 0; j < KT; j++) {
            float pj = __shfl_sync(0xffffffffu, (j < 32) ? e0 : ((j < 64) ? e1 : e2), j & 31);
            acc += pj * Vs[j][lane];
        }
        acc *= inv;
        g_att[(((size_t)bi*NN + n)*HH + h)*DD + lane] = acc;
    }
}

extern "C" void kernel_launch(void* const* d_in, const int* in_sizes, int n_in,
                              void* d_out, int out_size) {
    const float* x      = (const float*)d_in[0];
    const float* w_qkv  = (const float*)d_in[1];
    const float* w_gp   = (const float*)d_in[2];
    const float* w_proj = (const float*)d_in[3];
    float* out = (float*)d_out;

    zero_kernel<<<144, 256>>>();
    gemm_nt<0><<<dim3(9, 25), 256>>>(x, w_qkv, nullptr);       // QKV: 3200x1152x384
    route_kernel<<<NQ/8, 256>>>(w_gp);
    qmw_topk_kernel<<<BHc*(GG/GPB), 256>>>();
    attn_kernel<<<NROW, 256>>>();
    gemm_nt<1><<<dim3(3, 25), 256>>>(nullptr, w_proj, out);    // proj: 3200x384x384
}